// round 16
// baseline (speedup 1.0000x reference)
#include <cuda_runtime.h>
#include <cuda_bf16.h>

// FourierBlock: y = irfft( pad_K( (rfft(q)[:, :64]) @ (Wr + i Wi) ) )
// Parity-folded (K halved), mma.sync bf16 hi/lo 3-term split throughout
// (tcgen05 unavailable: harness targets plain sm_100).
// inv: B-resident Y, sequential parity with smem stash (one 32-reg
// accumulator live at a time -> register relief for the scheduler).

#define L_LEN 4096
#define LH 2048
#define NB 8
#define NH 8
#define KF 64
#define NC 512
#define RSPLIT 4

// ---- scratch (all __device__ globals; no allocs) ----
__device__ __align__(16) __nv_bfloat16 g_fb_h[128 * LH];   // [perm_row][l<2048]
__device__ __align__(16) __nv_bfloat16 g_fb_l[128 * LH];
__device__ __align__(16) __nv_bfloat16 g_ib_h[LH * 128];   // [l<2048][perm_col]
__device__ __align__(16) __nv_bfloat16 g_ib_l[LH * 128];
__device__ __align__(16) __nv_bfloat16 g_Y_h[NB * 128 * NC];
__device__ __align__(16) __nv_bfloat16 g_Y_l[NB * 128 * NC];
__device__ __align__(16) float g_Xpart[RSPLIT * NB * 128 * NC];

__device__ __forceinline__ void split2(float v, __nv_bfloat16& h, __nv_bfloat16& l) {
    h = __float2bfloat16(v);
    l = __float2bfloat16(v - __bfloat162float(h));
}

// ---------------------------------------------------------------------------
// Basis init, parity-permuted, half length.
// ---------------------------------------------------------------------------
__global__ __launch_bounds__(256) void init_kernel() {
    int idx = blockIdx.x * blockDim.x + threadIdx.x;
    if (idx >= 128 * LH) return;
    int r = idx >> 11;
    int l = idx & (LH - 1);
    int p = r >> 6;
    int w = r & 63;
    int j = w & 31;
    int k = 2 * j + p;
    int m = (k * l) & (L_LEN - 1);
    float s, c;
    sincospif(2.0f * (float)m / 4096.0f, &s, &c);
    float v = (w < 32) ? c : -s;
    __nv_bfloat16 h, lo;
    split2(v, h, lo);
    g_fb_h[r * LH + l] = h;   g_fb_l[r * LH + l] = lo;
    g_ib_h[l * 128 + r] = h;  g_ib_l[l * 128 + r] = lo;
}

#define CP_ASYNC16(dst_u32, src) \
    asm volatile("cp.async.cg.shared.global [%0], [%1], 16;\n" :: "r"(dst_u32), "l"(src))
#define CP_COMMIT() asm volatile("cp.async.commit_group;\n" ::)
#define CP_WAIT1() asm volatile("cp.async.wait_group 1;\n" ::)
#define CP_WAIT0() asm volatile("cp.async.wait_group 0;\n" ::)

#define MMA_BF16(ACC, A0, A1, A2, A3, B0, B1)                                  \
    asm volatile("mma.sync.aligned.m16n8k16.row.col.f32.bf16.bf16.f32 "        \
                 "{%0,%1,%2,%3}, {%4,%5,%6,%7}, {%8,%9}, {%0,%1,%2,%3};"       \
                 : "+f"(ACC[0]), "+f"(ACC[1]), "+f"(ACC[2]), "+f"(ACC[3])      \
                 : "r"(A0), "r"(A1), "r"(A2), "r"(A3), "r"(B0), "r"(B1))

#define LDMX4(F, ADDR)                                                          \
    asm volatile("ldmatrix.sync.aligned.m8n8.x4.shared.b16 {%0,%1,%2,%3}, [%4];"\
                 : "=r"(F[0]), "=r"(F[1]), "=r"(F[2]), "=r"(F[3]) : "r"(ADDR))
#define LDMX2T(F, ADDR)                                                         \
    asm volatile("ldmatrix.sync.aligned.m8n8.x2.trans.shared.b16 {%0,%1}, [%2];"\
                 : "=r"(F[0]), "=r"(F[1]) : "r"(ADDR))

#define STCS2(p, vx, vy)                                                        \
    asm volatile("st.global.cs.v2.f32 [%0], {%1, %2};"                          \
                 :: "l"(p), "f"(vx), "f"(vy) : "memory")

// ---------------------------------------------------------------------------
// Forward GEMM, parity-folded (R13 winner, unchanged).
// 128x64 CTA tile, 8 warps 4x2, K-chunk 32, split-K 4.
// ---------------------------------------------------------------------------
#define FTKC 32
#define FASTR 40
#define FATILE (128 * FASTR * 2)       // 10240
#define FBSTR 72
#define FBT (FTKC * FBSTR * 2)         // 4608
#define FBUF (2 * FATILE + 4 * FBT)    // 38912

__global__ __launch_bounds__(256, 2) void fwd_gemm(const float* __restrict__ Bf32) {
    constexpr int NCHUNK = (LH / RSPLIT) / FTKC;   // 16

    const int b = blockIdx.z;
    const int col0 = blockIdx.x * 64;
    const int kbeg = blockIdx.y * (LH / RSPLIT);
    const float* Bq = Bf32 + (size_t)b * (L_LEN * NC);
    float* Cb = g_Xpart + ((size_t)blockIdx.y * NB + b) * (128 * NC);

    extern __shared__ __align__(16) char smem[];
    const unsigned su = (unsigned)__cvta_generic_to_shared(smem);
    const int tid = threadIdx.x;
    const int lane = tid & 31, wid = tid >> 5;
    const int wm = wid & 3, wn = wid >> 2;
    const int sel = wm >> 1;

    float acc[2][4][4];
#pragma unroll
    for (int mi = 0; mi < 2; mi++)
#pragma unroll
        for (int ni = 0; ni < 4; ni++)
#pragma unroll
            for (int r = 0; r < 4; r++) acc[mi][ni][r] = 0.0f;

    auto prefetchA = [&](int ch) {
        const int k0 = kbeg + ch * FTKC;
        const unsigned base = su + (ch & 1) * FBUF;
#pragma unroll
        for (int i = 0; i < 2; i++) {
            int idx = tid + i * 256;
            int r = idx >> 2, s8 = idx & 3;
            const size_t off = (size_t)r * LH + k0 + s8 * 8;
            CP_ASYNC16(base + r * (FASTR * 2) + s8 * 16, g_fb_h + off);
            CP_ASYNC16(base + FATILE + r * (FASTR * 2) + s8 * 16, g_fb_l + off);
        }
        CP_COMMIT();
    };

    float4 ra[2], rb[2];
    auto ldgB = [&](int ch) {
        const int k0 = kbeg + ch * FTKC;
#pragma unroll
        for (int i = 0; i < 2; i++) {
            int idx = tid + i * 256;
            int r = idx >> 4, c4 = idx & 15;
            ra[i] = *(const float4*)(Bq + (size_t)(k0 + r) * NC + col0 + c4 * 4);
            rb[i] = *(const float4*)(Bq + (size_t)(k0 + r + LH) * NC + col0 + c4 * 4);
        }
    };
    auto stsB = [&](int ch) {
        char* base = smem + (ch & 1) * FBUF + 2 * FATILE;
#pragma unroll
        for (int i = 0; i < 2; i++) {
            int idx = tid + i * 256;
            int r = idx >> 4, c4 = idx & 15;
            const int off = r * (FBSTR * 2) + c4 * 8;
            float ev[4] = {ra[i].x + rb[i].x, ra[i].y + rb[i].y,
                           ra[i].z + rb[i].z, ra[i].w + rb[i].w};
            float ov[4] = {ra[i].x - rb[i].x, ra[i].y - rb[i].y,
                           ra[i].z - rb[i].z, ra[i].w - rb[i].w};
            __nv_bfloat16 h0, l0, h1, l1, h2, l2, h3, l3;
            split2(ev[0], h0, l0); split2(ev[1], h1, l1);
            split2(ev[2], h2, l2); split2(ev[3], h3, l3);
            ((__nv_bfloat162*)(base + off))[0] = __nv_bfloat162(h0, h1);
            ((__nv_bfloat162*)(base + off))[1] = __nv_bfloat162(h2, h3);
            ((__nv_bfloat162*)(base + FBT + off))[0] = __nv_bfloat162(l0, l1);
            ((__nv_bfloat162*)(base + FBT + off))[1] = __nv_bfloat162(l2, l3);
            split2(ov[0], h0, l0); split2(ov[1], h1, l1);
            split2(ov[2], h2, l2); split2(ov[3], h3, l3);
            ((__nv_bfloat162*)(base + 2 * FBT + off))[0] = __nv_bfloat162(h0, h1);
            ((__nv_bfloat162*)(base + 2 * FBT + off))[1] = __nv_bfloat162(h2, h3);
            ((__nv_bfloat162*)(base + 3 * FBT + off))[0] = __nv_bfloat162(l0, l1);
            ((__nv_bfloat162*)(base + 3 * FBT + off))[1] = __nv_bfloat162(l2, l3);
        }
    };

    ldgB(0);
    prefetchA(0);

    for (int it = 0; it < NCHUNK; it++) {
        stsB(it);
        if (it + 1 < NCHUNK) { ldgB(it + 1); prefetchA(it + 1); CP_WAIT1(); }
        else { CP_WAIT0(); }
        __syncthreads();

        const unsigned base = su + (it & 1) * FBUF;
        const unsigned bpar = base + 2 * FATILE + sel * (2 * FBT);
#pragma unroll
        for (int kstep = 0; kstep < 2; kstep++) {
            unsigned fah[2][4], fal[2][4], fbh[4][2], fbl[4][2];
#pragma unroll
            for (int mi = 0; mi < 2; mi++) {
                unsigned addr = base +
                    (unsigned)((wm * 32 + mi * 16 + (lane & 15)) * (FASTR * 2) +
                               kstep * 32 + (lane >> 4) * 16);
                LDMX4(fah[mi], addr);
                LDMX4(fal[mi], addr + FATILE);
            }
            const unsigned brow = (unsigned)((kstep * 16 + (lane & 15)) * (FBSTR * 2) +
                                             (wn * 32) * 2);
#pragma unroll
            for (int ni = 0; ni < 4; ni++) {
                LDMX2T(fbh[ni], bpar + brow + ni * 16);
                LDMX2T(fbl[ni], bpar + FBT + brow + ni * 16);
            }
#pragma unroll
            for (int mi = 0; mi < 2; mi++)
#pragma unroll
                for (int ni = 0; ni < 4; ni++) {
                    MMA_BF16(acc[mi][ni], fah[mi][0], fah[mi][1], fah[mi][2], fah[mi][3],
                             fbh[ni][0], fbh[ni][1]);
                    MMA_BF16(acc[mi][ni], fah[mi][0], fah[mi][1], fah[mi][2], fah[mi][3],
                             fbl[ni][0], fbl[ni][1]);
                    MMA_BF16(acc[mi][ni], fal[mi][0], fal[mi][1], fal[mi][2], fal[mi][3],
                             fbh[ni][0], fbh[ni][1]);
                }
        }
        __syncthreads();
    }

    const int g = lane >> 2, tig = lane & 3;
#pragma unroll
    for (int mi = 0; mi < 2; mi++)
#pragma unroll
        for (int ni = 0; ni < 4; ni++) {
            int r = wm * 32 + mi * 16 + g;
            int c = col0 + wn * 32 + ni * 8 + tig * 2;
            *(float2*)&Cb[(size_t)r * NC + c] = make_float2(acc[mi][ni][0], acc[mi][ni][1]);
            *(float2*)&Cb[(size_t)(r + 8) * NC + c] = make_float2(acc[mi][ni][2], acc[mi][ni][3]);
        }
}

// ---------------------------------------------------------------------------
// Inverse GEMM, parity-folded + B-resident, sequential parity + smem stash.
// B: Y[128 perm-k x 64 n] hi/lo resident (36 KB).
// A: ibasis sub-chunks of 128 rows x 32 k (20.5 KB/buffer, double-buffered).
// Per mb: accumulate parity-e into acc, stash to smem (per-thread private,
// conflict-free), re-zero, accumulate parity-o, epilogue combines.
// ---------------------------------------------------------------------------
#define IVASTR 40
#define IVA_MAT (128 * IVASTR * 2)        // 10240 (one 128x32 matrix)
#define IVA_BUF (2 * IVA_MAT)             // 20480 (hi+lo)
#define IVB_STR 72
#define IVB_MAT (128 * IVB_STR * 2)       // 18432
#define IVA_OFF (2 * IVB_MAT)             // 36864
#define IVS_OFF (IVA_OFF + 2 * IVA_BUF)   // 77824 (stash, 32 KB)
#define IV_SMEM (IVS_OFF + 32768)         // 110592

#define INV_KSTEPS(ACC, ABASE, KOFF)                                            \
    _Pragma("unroll")                                                           \
    for (int kstep = 0; kstep < 2; kstep++) {                                   \
        unsigned fah[2][4], fal[2][4], fbh[4][2], fbl[4][2];                    \
        _Pragma("unroll")                                                       \
        for (int mi = 0; mi < 2; mi++) {                                        \
            unsigned addr = (ABASE) +                                           \
                (unsigned)((wm * 32 + mi * 16 + (lane & 15)) * (IVASTR * 2) +   \
                           kstep * 32 + (lane >> 4) * 16);                      \
            LDMX4(fah[mi], addr);                                               \
            LDMX4(fal[mi], addr + IVA_MAT);                                     \
        }                                                                       \
        const unsigned brow = su +                                              \
            (unsigned)(((KOFF) + kstep * 16 + (lane & 15)) * (IVB_STR * 2) +    \
                       (wn * 32) * 2);                                          \
        _Pragma("unroll")                                                       \
        for (int ni = 0; ni < 4; ni++) {                                        \
            LDMX2T(fbh[ni], brow + ni * 16);                                    \
            LDMX2T(fbl[ni], brow + IVB_MAT + ni * 16);                          \
        }                                                                       \
        _Pragma("unroll")                                                       \
        for (int mi = 0; mi < 2; mi++)                                          \
            _Pragma("unroll")                                                   \
            for (int ni = 0; ni < 4; ni++) {                                    \
                MMA_BF16(ACC[mi][ni], fah[mi][0], fah[mi][1], fah[mi][2],       \
                         fah[mi][3], fbh[ni][0], fbh[ni][1]);                   \
                MMA_BF16(ACC[mi][ni], fah[mi][0], fah[mi][1], fah[mi][2],       \
                         fah[mi][3], fbl[ni][0], fbl[ni][1]);                   \
                MMA_BF16(ACC[mi][ni], fal[mi][0], fal[mi][1], fal[mi][2],       \
                         fal[mi][3], fbh[ni][0], fbh[ni][1]);                   \
            }                                                                   \
    }

__global__ __launch_bounds__(256, 2) void inv_gemm(float* __restrict__ Cext) {
    const int b = blockIdx.z;
    const int col0 = blockIdx.x * 64;
    const int m0 = blockIdx.y * 256;      // l-base within [0, 2048)
    const __nv_bfloat16* Bh = g_Y_h + (size_t)b * (128 * NC);
    const __nv_bfloat16* Bl = g_Y_l + (size_t)b * (128 * NC);
    float* Cb = Cext + (size_t)b * (L_LEN * NC);

    extern __shared__ __align__(16) char smem[];
    const unsigned su = (unsigned)__cvta_generic_to_shared(smem);
    float* stash = (float*)(smem + IVS_OFF);
    const int tid = threadIdx.x;
    const int lane = tid & 31, wid = tid >> 5;
    const int wm = wid & 3, wn = wid >> 2;

    // Stage B (Y hi/lo, all 128 perm-k rows), grouped with A0 commit.
#pragma unroll
    for (int i = 0; i < 4; i++) {
        int idx = tid + i * 256;
        int r = idx >> 3, s8 = idx & 7;
        const size_t off = (size_t)r * NC + col0 + s8 * 8;
        CP_ASYNC16(su + r * (IVB_STR * 2) + s8 * 16, Bh + off);
        CP_ASYNC16(su + IVB_MAT + r * (IVB_STR * 2) + s8 * 16, Bl + off);
    }

    auto prefA = [&](int it) {   // it = mb*4 + c*2 + sub
        const int mb = it >> 2, c = (it >> 1) & 1, sub = it & 1;
        const unsigned base = su + IVA_OFF + (it & 1) * IVA_BUF;
#pragma unroll
        for (int i = 0; i < 2; i++) {
            int idx = tid + i * 256;
            int r = idx >> 2, gg = idx & 3;
            const size_t off = (size_t)(m0 + mb * 128 + r) * 128 + c * 64 + sub * 32 + gg * 8;
            CP_ASYNC16(base + r * (IVASTR * 2) + gg * 16, g_ib_h + off);
            CP_ASYNC16(base + IVA_MAT + r * (IVASTR * 2) + gg * 16, g_ib_l + off);
        }
        CP_COMMIT();
    };

    prefA(0);   // group 0 = B + A0

    float acc[2][4][4];
#pragma unroll
    for (int mi = 0; mi < 2; mi++)
#pragma unroll
        for (int ni = 0; ni < 4; ni++)
#pragma unroll
            for (int r = 0; r < 4; r++) acc[mi][ni][r] = 0.0f;

    const int g = lane >> 2, tig = lane & 3;

#pragma unroll
    for (int mb = 0; mb < 2; mb++) {
        // ---- parity e (c=0): two A sub-chunks ----
#pragma unroll
        for (int sub = 0; sub < 2; sub++) {
            const int it = mb * 4 + sub;
            prefA(it + 1);
            CP_WAIT1();
            __syncthreads();
            const unsigned abase = su + IVA_OFF + (it & 1) * IVA_BUF;
            INV_KSTEPS(acc, abase, sub * 32)
            __syncthreads();
        }
        // stash e, reset acc (per-thread private slots; no sync needed)
#pragma unroll
        for (int mi = 0; mi < 2; mi++)
#pragma unroll
            for (int ni = 0; ni < 4; ni++)
#pragma unroll
                for (int r = 0; r < 4; r++) {
                    stash[((mi * 4 + ni) * 4 + r) * 256 + tid] = acc[mi][ni][r];
                    acc[mi][ni][r] = 0.0f;
                }
        // ---- parity o (c=1): two A sub-chunks ----
#pragma unroll
        for (int sub = 0; sub < 2; sub++) {
            const int it = mb * 4 + 2 + sub;
            if (it + 1 < 8) { prefA(it + 1); CP_WAIT1(); }
            else { CP_WAIT0(); }
            __syncthreads();
            const unsigned abase = su + IVA_OFF + (it & 1) * IVA_BUF;
            INV_KSTEPS(acc, abase, 64 + sub * 32)
            __syncthreads();
        }

        // epilogue: combine stash(e) + acc(o), streaming-store, reset
#pragma unroll
        for (int mi = 0; mi < 2; mi++)
#pragma unroll
            for (int ni = 0; ni < 4; ni++) {
                int r = m0 + mb * 128 + wm * 32 + mi * 16 + g;
                int cc = col0 + wn * 32 + ni * 8 + tig * 2;
                float e0 = stash[((mi * 4 + ni) * 4 + 0) * 256 + tid];
                float e1 = stash[((mi * 4 + ni) * 4 + 1) * 256 + tid];
                float e2 = stash[((mi * 4 + ni) * 4 + 2) * 256 + tid];
                float e3 = stash[((mi * 4 + ni) * 4 + 3) * 256 + tid];
                float o0 = acc[mi][ni][0], o1 = acc[mi][ni][1];
                float o2 = acc[mi][ni][2], o3 = acc[mi][ni][3];
                STCS2(&Cb[(size_t)r * NC + cc], e0 + o0, e1 + o1);
                STCS2(&Cb[(size_t)(r + 8) * NC + cc], e2 + o2, e3 + o3);
                STCS2(&Cb[(size_t)(r + LH) * NC + cc], e0 - o0, e1 - o1);
                STCS2(&Cb[(size_t)(r + LH + 8) * NC + cc], e2 - o2, e3 - o3);
#pragma unroll
                for (int q = 0; q < 4; q++) acc[mi][ni][q] = 0.0f;
            }
    }
}

// ---------------------------------------------------------------------------
// Split-K reduce + per-(k,h) complex mix; permuted row indexing:
// real row = (k&1)*64 + (k>>1), imag row = +32.
// ---------------------------------------------------------------------------
__global__ __launch_bounds__(512) void einsum_kernel(const float* __restrict__ Wr,
                                                     const float* __restrict__ Wi) {
    __shared__ float sWr[64][64];
    __shared__ float sWi[64][64];
    __shared__ float sXr[8][64];
    __shared__ float sXi[8][64];

    const int kh = blockIdx.x;
    const int k = kh >> 3;
    const int h = kh & 7;
    const int tid = threadIdx.x;
    const int base = ((k & 1) << 6) + (k >> 1);

    const float4* wr4 = (const float4*)(Wr + (size_t)kh * 4096);
    const float4* wi4 = (const float4*)(Wi + (size_t)kh * 4096);
    float4* sWr4 = (float4*)sWr;
    float4* sWi4 = (float4*)sWi;
#pragma unroll
    for (int e = 0; e < 2; e++) {
        sWr4[tid + e * 512] = wr4[tid + e * 512];
        sWi4[tid + e * 512] = wi4[tid + e * 512];
    }
    {
        const int b = tid >> 6, i = tid & 63;
        float sr = 0.f, si = 0.f;
        const float* p = g_Xpart + (size_t)b * (128 * NC) + (size_t)base * NC + h * 64 + i;
#pragma unroll
        for (int s = 0; s < RSPLIT; s++) {
            sr += p[0];
            si += p[32 * NC];
            p += (size_t)NB * 128 * NC;
        }
        sXr[b][i] = sr;
        sXi[b][i] = si;
    }
    __syncthreads();

    const int o = tid & 63;
    const int bb = tid >> 6;
    const float w = (k == 0 ? 1.0f : 2.0f) / (float)L_LEN;
    float ar = 0.f, ai = 0.f;
#pragma unroll
    for (int i = 0; i < 64; i++) {
        const float xr = sXr[bb][i], xi = sXi[bb][i];
        const float wrv = sWr[i][o], wiv = sWi[i][o];
        ar += xr * wrv - xi * wiv;
        ai += xr * wiv + xi * wrv;
    }
    const size_t pr = (size_t)bb * (128 * NC) + (size_t)base * NC + h * 64 + o;
    const size_t pi = pr + (size_t)32 * NC;
    __nv_bfloat16 hh, ll;
    split2(ar * w, hh, ll);
    g_Y_h[pr] = hh; g_Y_l[pr] = ll;
    split2(ai * w, hh, ll);
    g_Y_h[pi] = hh; g_Y_l[pi] = ll;
}

// ---------------------------------------------------------------------------
// inputs (metadata order): q, k, v, W_real, W_imag, mask
// ---------------------------------------------------------------------------
extern "C" void kernel_launch(void* const* d_in, const int* in_sizes, int n_in,
                              void* d_out, int out_size) {
    const float* q  = (const float*)d_in[0];
    const float* Wr = (const float*)d_in[3];
    const float* Wi = (const float*)d_in[4];
    float* out = (float*)d_out;

    static bool attr_done = false;
    if (!attr_done) {
        cudaFuncSetAttribute(fwd_gemm, cudaFuncAttributeMaxDynamicSharedMemorySize,
                             2 * FBUF);
        cudaFuncSetAttribute(inv_gemm, cudaFuncAttributeMaxDynamicSharedMemorySize,
                             IV_SMEM);
        attr_done = true;
    }

    init_kernel<<<(128 * LH + 255) / 256, 256>>>();
    fwd_gemm<<<dim3(8, RSPLIT, NB), 256, 2 * FBUF>>>(q);
    einsum_kernel<<<KF * NH, 512>>>(Wr, Wi);
    inv_gemm<<<dim3(8, LH / 256, NB), 256, IV_SMEM>>>(out);
}

// round 17
// speedup vs baseline: 1.3026x; 1.3026x over previous
#include <cuda_runtime.h>
#include <cuda_bf16.h>
#include <cuda_fp16.h>

// FourierBlock: y = irfft( pad_K( (rfft(q)[:, :64]) @ (Wr + i Wi) ) )
// Parity-folded (K halved). fp16 2-term split: basis single fp16 (2^-11),
// data side hi/lo fp16 (2^-22). Y pre-scaled by exact 2^20 (fp16 subnormal
// avoidance); inverse epilogue applies exact 2^-20.

#define L_LEN 4096
#define LH 2048
#define NB 8
#define NH 8
#define KF 64
#define NC 512
#define RSPLIT 4
#define OUTSCALE 9.5367431640625e-7f   // 2^-20 exact

// ---- scratch (all __device__ globals; no allocs) ----
__device__ __align__(16) __half g_fb[128 * LH];    // [perm_row][l<2048]
__device__ __align__(16) __half g_ib[LH * 128];    // [l<2048][perm_col]
__device__ __align__(16) __half g_Y_h[NB * 128 * NC];
__device__ __align__(16) __half g_Y_l[NB * 128 * NC];
__device__ __align__(16) float g_Xpart[RSPLIT * NB * 128 * NC];

__device__ __forceinline__ void split2h(float v, __half& h, __half& l) {
    h = __float2half_rn(v);
    l = __float2half_rn(v - __half2float(h));
}

// ---------------------------------------------------------------------------
// Basis init, parity-permuted, half length, single fp16.
// ---------------------------------------------------------------------------
__global__ __launch_bounds__(256) void init_kernel() {
    int idx = blockIdx.x * blockDim.x + threadIdx.x;
    if (idx >= 128 * LH) return;
    int r = idx >> 11;
    int l = idx & (LH - 1);
    int p = r >> 6;
    int w = r & 63;
    int j = w & 31;
    int k = 2 * j + p;
    int m = (k * l) & (L_LEN - 1);
    float s, c;
    sincospif(2.0f * (float)m / 4096.0f, &s, &c);
    float v = (w < 32) ? c : -s;
    __half hv = __float2half_rn(v);
    g_fb[r * LH + l] = hv;
    g_ib[l * 128 + r] = hv;
}

#define CP_ASYNC16(dst_u32, src) \
    asm volatile("cp.async.cg.shared.global [%0], [%1], 16;\n" :: "r"(dst_u32), "l"(src))
#define CP_COMMIT() asm volatile("cp.async.commit_group;\n" ::)
#define CP_WAIT1() asm volatile("cp.async.wait_group 1;\n" ::)
#define CP_WAIT0() asm volatile("cp.async.wait_group 0;\n" ::)

#define MMA_F16(ACC, A0, A1, A2, A3, B0, B1)                                   \
    asm volatile("mma.sync.aligned.m16n8k16.row.col.f32.f16.f16.f32 "          \
                 "{%0,%1,%2,%3}, {%4,%5,%6,%7}, {%8,%9}, {%0,%1,%2,%3};"       \
                 : "+f"(ACC[0]), "+f"(ACC[1]), "+f"(ACC[2]), "+f"(ACC[3])      \
                 : "r"(A0), "r"(A1), "r"(A2), "r"(A3), "r"(B0), "r"(B1))

#define LDMX4(F, ADDR)                                                          \
    asm volatile("ldmatrix.sync.aligned.m8n8.x4.shared.b16 {%0,%1,%2,%3}, [%4];"\
                 : "=r"(F[0]), "=r"(F[1]), "=r"(F[2]), "=r"(F[3]) : "r"(ADDR))
#define LDMX2T(F, ADDR)                                                         \
    asm volatile("ldmatrix.sync.aligned.m8n8.x2.trans.shared.b16 {%0,%1}, [%2];"\
                 : "=r"(F[0]), "=r"(F[1]) : "r"(ADDR))

// ---------------------------------------------------------------------------
// Forward GEMM, parity-folded, fp16 2-term:
// X[128perm, 512] = Fperm[128, 2048] @ {qe|qo}, terms A*Bh + A*Bl.
// 128x64 CTA tile, 8 warps 4x2 (32x32 each), K-chunk 32, split-K 4.
// ---------------------------------------------------------------------------
#define FTKC 32
#define FASTR 40
#define FATILE (128 * FASTR * 2)       // 10240 (single A matrix)
#define FBSTR 72
#define FBT (FTKC * FBSTR * 2)         // 4608
#define FBUF (FATILE + 4 * FBT)        // 28672

__global__ __launch_bounds__(256, 2) void fwd_gemm(const float* __restrict__ Bf32) {
    constexpr int NCHUNK = (LH / RSPLIT) / FTKC;   // 16

    const int b = blockIdx.z;
    const int col0 = blockIdx.x * 64;
    const int kbeg = blockIdx.y * (LH / RSPLIT);
    const float* Bq = Bf32 + (size_t)b * (L_LEN * NC);
    float* Cb = g_Xpart + ((size_t)blockIdx.y * NB + b) * (128 * NC);

    extern __shared__ __align__(16) char smem[];
    const unsigned su = (unsigned)__cvta_generic_to_shared(smem);
    const int tid = threadIdx.x;
    const int lane = tid & 31, wid = tid >> 5;
    const int wm = wid & 3, wn = wid >> 2;
    const int sel = wm >> 1;          // 0: even-k rows -> qe,  1: odd -> qo

    float acc[2][4][4];
#pragma unroll
    for (int mi = 0; mi < 2; mi++)
#pragma unroll
        for (int ni = 0; ni < 4; ni++)
#pragma unroll
            for (int r = 0; r < 4; r++) acc[mi][ni][r] = 0.0f;

    auto prefetchA = [&](int ch) {
        const int k0 = kbeg + ch * FTKC;
        const unsigned base = su + (ch & 1) * FBUF;
#pragma unroll
        for (int i = 0; i < 2; i++) {
            int idx = tid + i * 256;
            int r = idx >> 2, s8 = idx & 3;
            CP_ASYNC16(base + r * (FASTR * 2) + s8 * 16,
                       g_fb + (size_t)r * LH + k0 + s8 * 8);
        }
        CP_COMMIT();
    };

    float4 ra[2], rb[2];
    auto ldgB = [&](int ch) {
        const int k0 = kbeg + ch * FTKC;
#pragma unroll
        for (int i = 0; i < 2; i++) {
            int idx = tid + i * 256;
            int r = idx >> 4, c4 = idx & 15;
            ra[i] = *(const float4*)(Bq + (size_t)(k0 + r) * NC + col0 + c4 * 4);
            rb[i] = *(const float4*)(Bq + (size_t)(k0 + r + LH) * NC + col0 + c4 * 4);
        }
    };
    auto stsB = [&](int ch) {
        char* base = smem + (ch & 1) * FBUF + FATILE;
#pragma unroll
        for (int i = 0; i < 2; i++) {
            int idx = tid + i * 256;
            int r = idx >> 4, c4 = idx & 15;
            const int off = r * (FBSTR * 2) + c4 * 8;
            float ev[4] = {ra[i].x + rb[i].x, ra[i].y + rb[i].y,
                           ra[i].z + rb[i].z, ra[i].w + rb[i].w};
            float ov[4] = {ra[i].x - rb[i].x, ra[i].y - rb[i].y,
                           ra[i].z - rb[i].z, ra[i].w - rb[i].w};
            __half h0, l0, h1, l1, h2, l2, h3, l3;
            split2h(ev[0], h0, l0); split2h(ev[1], h1, l1);
            split2h(ev[2], h2, l2); split2h(ev[3], h3, l3);
            ((__half2*)(base + off))[0] = __half2(h0, h1);
            ((__half2*)(base + off))[1] = __half2(h2, h3);
            ((__half2*)(base + FBT + off))[0] = __half2(l0, l1);
            ((__half2*)(base + FBT + off))[1] = __half2(l2, l3);
            split2h(ov[0], h0, l0); split2h(ov[1], h1, l1);
            split2h(ov[2], h2, l2); split2h(ov[3], h3, l3);
            ((__half2*)(base + 2 * FBT + off))[0] = __half2(h0, h1);
            ((__half2*)(base + 2 * FBT + off))[1] = __half2(h2, h3);
            ((__half2*)(base + 3 * FBT + off))[0] = __half2(l0, l1);
            ((__half2*)(base + 3 * FBT + off))[1] = __half2(l2, l3);
        }
    };

    ldgB(0);
    prefetchA(0);

    for (int it = 0; it < NCHUNK; it++) {
        stsB(it);
        if (it + 1 < NCHUNK) { ldgB(it + 1); prefetchA(it + 1); CP_WAIT1(); }
        else { CP_WAIT0(); }
        __syncthreads();

        const unsigned base = su + (it & 1) * FBUF;
        const unsigned bpar = base + FATILE + sel * (2 * FBT);
#pragma unroll
        for (int kstep = 0; kstep < 2; kstep++) {
            unsigned fah[2][4], fbh[4][2], fbl[4][2];
#pragma unroll
            for (int mi = 0; mi < 2; mi++) {
                unsigned addr = base +
                    (unsigned)((wm * 32 + mi * 16 + (lane & 15)) * (FASTR * 2) +
                               kstep * 32 + (lane >> 4) * 16);
                LDMX4(fah[mi], addr);
            }
            const unsigned brow = (unsigned)((kstep * 16 + (lane & 15)) * (FBSTR * 2) +
                                             (wn * 32) * 2);
#pragma unroll
            for (int ni = 0; ni < 4; ni++) {
                LDMX2T(fbh[ni], bpar + brow + ni * 16);
                LDMX2T(fbl[ni], bpar + FBT + brow + ni * 16);
            }
#pragma unroll
            for (int mi = 0; mi < 2; mi++)
#pragma unroll
                for (int ni = 0; ni < 4; ni++) {
                    MMA_F16(acc[mi][ni], fah[mi][0], fah[mi][1], fah[mi][2], fah[mi][3],
                            fbh[ni][0], fbh[ni][1]);
                    MMA_F16(acc[mi][ni], fah[mi][0], fah[mi][1], fah[mi][2], fah[mi][3],
                            fbl[ni][0], fbl[ni][1]);
                }
        }
        __syncthreads();
    }

    const int g = lane >> 2, tig = lane & 3;
#pragma unroll
    for (int mi = 0; mi < 2; mi++)
#pragma unroll
        for (int ni = 0; ni < 4; ni++) {
            int r = wm * 32 + mi * 16 + g;
            int c = col0 + wn * 32 + ni * 8 + tig * 2;
            *(float2*)&Cb[(size_t)r * NC + c] = make_float2(acc[mi][ni][0], acc[mi][ni][1]);
            *(float2*)&Cb[(size_t)(r + 8) * NC + c] = make_float2(acc[mi][ni][2], acc[mi][ni][3]);
        }
}

// ---------------------------------------------------------------------------
// Inverse GEMM, parity-folded + B-resident, fp16 2-term (R13 structure).
// B: Y[128 perm-k x 64 n] hi/lo fp16, pre-scaled 2^20, resident (36 KB).
// A: ibasis single fp16 chunks 128x64 (18 KB/buffer, double-buffered).
// accE/accO static; epilogue y[l]=(e+o)*2^-20, y[l+2048]=(e-o)*2^-20.
// ---------------------------------------------------------------------------
#define IVSTR 72
#define IV_MAT (128 * IVSTR * 2)          // 18432
#define IVA_OFF (2 * IV_MAT)              // 36864 (after B h/l)
#define IVA_BUF IV_MAT                    // 18432 (single A matrix)
#define IV_SMEM (IVA_OFF + 2 * IVA_BUF)   // 73728

#define INV_KSTEPS(ACC, ABASE, CC)                                              \
    _Pragma("unroll")                                                           \
    for (int kstep = 0; kstep < 4; kstep++) {                                   \
        unsigned fah[2][4], fbh[4][2], fbl[4][2];                               \
        _Pragma("unroll")                                                       \
        for (int mi = 0; mi < 2; mi++) {                                        \
            unsigned addr = (ABASE) +                                           \
                (unsigned)((wm * 32 + mi * 16 + (lane & 15)) * (IVSTR * 2) +    \
                           kstep * 32 + (lane >> 4) * 16);                      \
            LDMX4(fah[mi], addr);                                               \
        }                                                                       \
        const unsigned brow = su +                                              \
            (unsigned)(((CC) * 64 + kstep * 16 + (lane & 15)) * (IVSTR * 2) +   \
                       (wn * 32) * 2);                                          \
        _Pragma("unroll")                                                       \
        for (int ni = 0; ni < 4; ni++) {                                        \
            LDMX2T(fbh[ni], brow + ni * 16);                                    \
            LDMX2T(fbl[ni], brow + IV_MAT + ni * 16);                           \
        }                                                                       \
        _Pragma("unroll")                                                       \
        for (int mi = 0; mi < 2; mi++)                                          \
            _Pragma("unroll")                                                   \
            for (int ni = 0; ni < 4; ni++) {                                    \
                MMA_F16(ACC[mi][ni], fah[mi][0], fah[mi][1], fah[mi][2],        \
                        fah[mi][3], fbh[ni][0], fbh[ni][1]);                    \
                MMA_F16(ACC[mi][ni], fah[mi][0], fah[mi][1], fah[mi][2],        \
                        fah[mi][3], fbl[ni][0], fbl[ni][1]);                    \
            }                                                                   \
    }

__global__ __launch_bounds__(256, 2) void inv_gemm(float* __restrict__ Cext) {
    const int b = blockIdx.z;
    const int col0 = blockIdx.x * 64;
    const int m0 = blockIdx.y * 256;      // l-base within [0, 2048)
    const __half* Bh = g_Y_h + (size_t)b * (128 * NC);
    const __half* Bl = g_Y_l + (size_t)b * (128 * NC);
    float* Cb = Cext + (size_t)b * (L_LEN * NC);

    extern __shared__ __align__(16) char smem[];
    const unsigned su = (unsigned)__cvta_generic_to_shared(smem);
    const int tid = threadIdx.x;
    const int lane = tid & 31, wid = tid >> 5;
    const int wm = wid & 3, wn = wid >> 2;

    // Stage B (Y hi/lo, all 128 perm-k rows), grouped with A0 commit.
#pragma unroll
    for (int i = 0; i < 4; i++) {
        int idx = tid + i * 256;
        int r = idx >> 3, s8 = idx & 7;
        const size_t off = (size_t)r * NC + col0 + s8 * 8;
        CP_ASYNC16(su + r * (IVSTR * 2) + s8 * 16, Bh + off);
        CP_ASYNC16(su + IV_MAT + r * (IVSTR * 2) + s8 * 16, Bl + off);
    }

    auto prefA = [&](int it) {             // it = mb*2 + c
        const int mb = it >> 1, c = it & 1;
        const unsigned base = su + IVA_OFF + (it & 1) * IVA_BUF;
#pragma unroll
        for (int i = 0; i < 4; i++) {
            int idx = tid + i * 256;
            int r = idx >> 3, s8 = idx & 7;
            CP_ASYNC16(base + r * (IVSTR * 2) + s8 * 16,
                       g_ib + (size_t)(m0 + mb * 128 + r) * 128 + c * 64 + s8 * 8);
        }
        CP_COMMIT();
    };

    prefA(0);

    float accE[2][4][4], accO[2][4][4];
#pragma unroll
    for (int mi = 0; mi < 2; mi++)
#pragma unroll
        for (int ni = 0; ni < 4; ni++)
#pragma unroll
            for (int r = 0; r < 4; r++) { accE[mi][ni][r] = 0.0f; accO[mi][ni][r] = 0.0f; }

    const int g = lane >> 2, tig = lane & 3;

#pragma unroll
    for (int mb = 0; mb < 2; mb++) {
        // ---- c = 0 (even-k columns -> accE) ----
        {
            const int it = mb * 2;
            prefA(it + 1);
            CP_WAIT1();
            __syncthreads();
            const unsigned abase = su + IVA_OFF + (it & 1) * IVA_BUF;
            INV_KSTEPS(accE, abase, 0)
            __syncthreads();
        }
        // ---- c = 1 (odd-k columns -> accO) ----
        {
            const int it = mb * 2 + 1;
            if (it + 1 < 4) { prefA(it + 1); CP_WAIT1(); }
            else { CP_WAIT0(); }
            __syncthreads();
            const unsigned abase = su + IVA_OFF + (it & 1) * IVA_BUF;
            INV_KSTEPS(accO, abase, 1)
        }

        // ---- epilogue: combine parities (exact 2^-20), write both halves ----
#pragma unroll
        for (int mi = 0; mi < 2; mi++)
#pragma unroll
            for (int ni = 0; ni < 4; ni++) {
                int r = m0 + mb * 128 + wm * 32 + mi * 16 + g;
                int cc = col0 + wn * 32 + ni * 8 + tig * 2;
                float e0 = accE[mi][ni][0], o0 = accO[mi][ni][0];
                float e1 = accE[mi][ni][1], o1 = accO[mi][ni][1];
                float e2 = accE[mi][ni][2], o2 = accO[mi][ni][2];
                float e3 = accE[mi][ni][3], o3 = accO[mi][ni][3];
                *(float2*)&Cb[(size_t)r * NC + cc] =
                    make_float2((e0 + o0) * OUTSCALE, (e1 + o1) * OUTSCALE);
                *(float2*)&Cb[(size_t)(r + 8) * NC + cc] =
                    make_float2((e2 + o2) * OUTSCALE, (e3 + o3) * OUTSCALE);
                *(float2*)&Cb[(size_t)(r + LH) * NC + cc] =
                    make_float2((e0 - o0) * OUTSCALE, (e1 - o1) * OUTSCALE);
                *(float2*)&Cb[(size_t)(r + LH + 8) * NC + cc] =
                    make_float2((e2 - o2) * OUTSCALE, (e3 - o3) * OUTSCALE);
#pragma unroll
                for (int q = 0; q < 4; q++) { accE[mi][ni][q] = 0.0f; accO[mi][ni][q] = 0.0f; }
            }
        __syncthreads();
    }
}

// ---------------------------------------------------------------------------
// Split-K reduce + per-(k,h) complex mix; permuted row indexing.
// Emits Y * 2^20 as fp16 hi/lo (w = exactly 256 or 512).
// ---------------------------------------------------------------------------
__global__ __launch_bounds__(512) void einsum_kernel(const float* __restrict__ Wr,
                                                     const float* __restrict__ Wi) {
    __shared__ float sWr[64][64];
    __shared__ float sWi[64][64];
    __shared__ float sXr[8][64];
    __shared__ float sXi[8][64];

    const int kh = blockIdx.x;
    const int k = kh >> 3;
    const int h = kh & 7;
    const int tid = threadIdx.x;
    const int base = ((k & 1) << 6) + (k >> 1);

    const float4* wr4 = (const float4*)(Wr + (size_t)kh * 4096);
    const float4* wi4 = (const float4*)(Wi + (size_t)kh * 4096);
    float4* sWr4 = (float4*)sWr;
    float4* sWi4 = (float4*)sWi;
#pragma unroll
    for (int e = 0; e < 2; e++) {
        sWr4[tid + e * 512] = wr4[tid + e * 512];
        sWi4[tid + e * 512] = wi4[tid + e * 512];
    }
    {
        const int b = tid >> 6, i = tid & 63;
        float sr = 0.f, si = 0.f;
        const float* p = g_Xpart + (size_t)b * (128 * NC) + (size_t)base * NC + h * 64 + i;
#pragma unroll
        for (int s = 0; s < RSPLIT; s++) {
            sr += p[0];
            si += p[32 * NC];
            p += (size_t)NB * 128 * NC;
        }
        sXr[b][i] = sr;
        sXi[b][i] = si;
    }
    __syncthreads();

    const int o = tid & 63;
    const int bb = tid >> 6;
    const float w = (k == 0 ? 256.0f : 512.0f);   // (1|2)/4096 * 2^20, exact
    float ar = 0.f, ai = 0.f;
#pragma unroll
    for (int i = 0; i < 64; i++) {
        const float xr = sXr[bb][i], xi = sXi[bb][i];
        const float wrv = sWr[i][o], wiv = sWi[i][o];
        ar += xr * wrv - xi * wiv;
        ai += xr * wiv + xi * wrv;
    }
    const size_t pr = (size_t)bb * (128 * NC) + (size_t)base * NC + h * 64 + o;
    const size_t pi = pr + (size_t)32 * NC;
    __half hh, ll;
    split2h(ar * w, hh, ll);
    g_Y_h[pr] = hh; g_Y_l[pr] = ll;
    split2h(ai * w, hh, ll);
    g_Y_h[pi] = hh; g_Y_l[pi] = ll;
}

// ---------------------------------------------------------------------------
// inputs (metadata order): q, k, v, W_real, W_imag, mask
// ---------------------------------------------------------------------------
extern "C" void kernel_launch(void* const* d_in, const int* in_sizes, int n_in,
                              void* d_out, int out_size) {
    const float* q  = (const float*)d_in[0];
    const float* Wr = (const float*)d_in[3];
    const float* Wi = (const float*)d_in[4];
    float* out = (float*)d_out;

    static bool attr_done = false;
    if (!attr_done) {
        cudaFuncSetAttribute(fwd_gemm, cudaFuncAttributeMaxDynamicSharedMemorySize,
                             2 * FBUF);
        cudaFuncSetAttribute(inv_gemm, cudaFuncAttributeMaxDynamicSharedMemorySize,
                             IV_SMEM);
        attr_done = true;
    }

    init_kernel<<<(128 * LH + 255) / 256, 256>>>();
    fwd_gemm<<<dim3(8, RSPLIT, NB), 256, 2 * FBUF>>>(q);
    einsum_kernel<<<KF * NH, 512>>>(Wr, Wi);
    inv_gemm<<<dim3(8, LH / 256, NB), 256, IV_SMEM>>>(out);
}